// round 8
// baseline (speedup 1.0000x reference)
#include <cuda_runtime.h>

// LIF neuron, T=4 unrolled — persistent grid-stride variant.
// Single wave: grid = 148 SMs x 8 blocks = 1184 blocks x 256 threads,
// each thread strides through the array processing 2 float4s (neurons)
// per iteration. Eliminates wave transitions / CTA launch-drain ramping
// present in the 32768-block versions.
// Loads front-batched with streaming hints (read-once), streaming stores.

#define TAU 0.25f

__device__ __forceinline__ float4 lif4(float4 xv, float4 lv, float thre)
{
    float4 ov;
    float u = xv.x + lv.x;                 // t=0: u0=0 -> no decay term
    float o = (u > thre) ? u : 0.0f;
    ov.x = o;
    float reset = (o > thre) ? 0.0f : 1.0f;
    u = TAU * u * reset + xv.y + lv.y;     // t=1
    o = (u > thre) ? u : 0.0f;
    ov.y = o;
    reset = (o > thre) ? 0.0f : 1.0f;
    u = TAU * u * reset + xv.z + lv.z;     // t=2
    o = (u > thre) ? u : 0.0f;
    ov.z = o;
    reset = (o > thre) ? 0.0f : 1.0f;
    u = TAU * u * reset + xv.w + lv.w;     // t=3
    o = (u > thre) ? u : 0.0f;
    ov.w = o;
    return ov;
}

__global__ __launch_bounds__(256) void lif_kernel_persist(
    const float4* __restrict__ x,
    const float4* __restrict__ lat,
    const float* __restrict__ w,
    float4* __restrict__ out,
    int n)   // n = B*N neurons (float4 elements)
{
    const float thre = tanhf(w[0]);

    // Each iteration covers gridDim.x * blockDim.x * 2 float4s.
    // Pair layout: thread handles i and i + blockDim.x -> both LDG.128
    // cover contiguous 512B warp segments.
    int stride = gridDim.x * blockDim.x * 2;
    int base = blockIdx.x * (blockDim.x * 2) + threadIdx.x;

    // Steady state: both indices in range (uniform loop condition).
    int i;
    for (i = base; i + blockDim.x < n ||
                   (i < n && i + blockDim.x < n); i += stride) {
        // (condition simplified below by splitting loop)
        break;
    }

    for (i = base; i + (int)blockDim.x < n; i += stride) {
        int i0 = i;
        int i1 = i + blockDim.x;
        float4 x0 = __ldcs(&x[i0]);
        float4 l0 = __ldcs(&lat[i0]);
        float4 x1 = __ldcs(&x[i1]);
        float4 l1 = __ldcs(&lat[i1]);
        __stcs(&out[i0], lif4(x0, l0, thre));
        __stcs(&out[i1], lif4(x1, l1, thre));
    }
    // Tail: at most one partial pair per thread.
    if (i < n) {
        float4 xv = __ldcs(&x[i]);
        float4 lv = __ldcs(&lat[i]);
        __stcs(&out[i], lif4(xv, lv, thre));
        int i1 = i + blockDim.x;
        if (i1 < n) {
            float4 xv1 = __ldcs(&x[i1]);
            float4 lv1 = __ldcs(&lat[i1]);
            __stcs(&out[i1], lif4(xv1, lv1, thre));
        }
    }
}

extern "C" void kernel_launch(void* const* d_in, const int* in_sizes, int n_in,
                              void* d_out, int out_size)
{
    const float4* x   = (const float4*)d_in[0];  // [B, N, T] float32, T=4
    const float4* lat = (const float4*)d_in[1];
    const float*  w   = (const float*)d_in[2];   // scalar
    float4* out = (float4*)d_out;

    int n = in_sizes[0] / 4;     // neurons (B*N); one float4 each

    int block = 256;
    int grid = 148 * 8;          // exactly one wave at 8 CTAs/SM (28 regs)
    // Don't launch more blocks than needed for tiny inputs.
    int max_grid = (n + block * 2 - 1) / (block * 2);
    if (grid > max_grid) grid = max_grid;
    if (grid < 1) grid = 1;

    lif_kernel_persist<<<grid, block>>>(x, lat, w, out, n);
}

// round 9
// speedup vs baseline: 1.1049x; 1.1049x over previous
#include <cuda_runtime.h>

// FINAL (reverted to measured optimum): LIF neuron, T=4 unrolled,
// 2 neurons (float4s) per thread, block=256, flat grid.
// Layout [B, N, T], T innermost -> one float4 per neuron.
// Front-batched 4x LDG.E.128 with streaming hints (read-once/write-once),
// exact-division fast path with zero predicates.
//
// Configuration space fully swept on GB300:
//   f4x2 blk256 (this):   108.6-109.7us kernel, 87-88% DRAM SOL  <- best
//   f4x1 / v8x2 / f4x4:   109.3-110.4us
//   blk512:               109.6us
//   persistent grid-stride: 120.5us (REGRESSED - oversubscribed flat grids
//     keep the memory queues fuller than a per-thread stride loop)
// Traffic (512MB read + 256MB write) is irreducible; ~7.0 TB/s achieved is
// the HBM3e mixed-R/W streaming ceiling on this part.

#define TAU 0.25f

__device__ __forceinline__ float4 lif4(float4 xv, float4 lv, float thre)
{
    float4 ov;
    float u = xv.x + lv.x;                 // t=0: u0=0 -> no decay term
    float o = (u > thre) ? u : 0.0f;
    ov.x = o;
    float reset = (o > thre) ? 0.0f : 1.0f;
    u = TAU * u * reset + xv.y + lv.y;     // t=1
    o = (u > thre) ? u : 0.0f;
    ov.y = o;
    reset = (o > thre) ? 0.0f : 1.0f;
    u = TAU * u * reset + xv.z + lv.z;     // t=2
    o = (u > thre) ? u : 0.0f;
    ov.z = o;
    reset = (o > thre) ? 0.0f : 1.0f;
    u = TAU * u * reset + xv.w + lv.w;     // t=3
    o = (u > thre) ? u : 0.0f;
    ov.w = o;
    return ov;
}

// Fast path: grid*blockDim*2 == n exactly; no predicates.
__global__ __launch_bounds__(256) void lif_kernel_exact(
    const float4* __restrict__ x,
    const float4* __restrict__ lat,
    const float* __restrict__ w,
    float4* __restrict__ out)
{
    int i0 = blockIdx.x * (blockDim.x * 2) + threadIdx.x;
    int i1 = i0 + blockDim.x;   // second contiguous 512B warp segment

    const float thre = tanhf(w[0]);

    // Front-batch all 4 loads (read-once: evict-first)
    float4 x0 = __ldcs(&x[i0]);
    float4 l0 = __ldcs(&lat[i0]);
    float4 x1 = __ldcs(&x[i1]);
    float4 l1 = __ldcs(&lat[i1]);

    __stcs(&out[i0], lif4(x0, l0, thre));
    __stcs(&out[i1], lif4(x1, l1, thre));
}

// Fallback: one float4 per thread, predicated (general sizes).
__global__ __launch_bounds__(256) void lif_kernel_f4(
    const float4* __restrict__ x,
    const float4* __restrict__ lat,
    const float* __restrict__ w,
    float4* __restrict__ out,
    int n)
{
    int i = blockIdx.x * blockDim.x + threadIdx.x;
    if (i >= n) return;
    const float thre = tanhf(w[0]);
    float4 xv = __ldcs(&x[i]);
    float4 lv = __ldcs(&lat[i]);
    __stcs(&out[i], lif4(xv, lv, thre));
}

extern "C" void kernel_launch(void* const* d_in, const int* in_sizes, int n_in,
                              void* d_out, int out_size)
{
    const float4* x   = (const float4*)d_in[0];  // [B, N, T] float32, T=4
    const float4* lat = (const float4*)d_in[1];
    const float*  w   = (const float*)d_in[2];   // scalar
    float4* out = (float4*)d_out;

    int n = in_sizes[0] / 4;     // neurons (B*N); one float4 each
    int block = 256;
    int per_block = block * 2;   // 2 neurons per thread

    if (n % per_block == 0) {
        lif_kernel_exact<<<n / per_block, block>>>(x, lat, w, out);
    } else {
        lif_kernel_f4<<<(n + block - 1) / block, block>>>(x, lat, w, out, n);
    }
}

// round 10
// speedup vs baseline: 1.1103x; 1.0049x over previous
#include <cuda_runtime.h>

// FINAL — converged optimum. LIF neuron, T=4 unrolled, 2 neurons (float4s)
// per thread, block=256, flat grid.
// Layout [B, N, T], T innermost -> one float4 per neuron.
// Front-batched 4x LDG.E.128 with streaming hints (read-once/write-once),
// exact-division fast path with zero predicates.
//
// Measurement record (GB300, 4 independent benches of this config):
//   kernel 108.6 / 108.7 / 109.7 / 109.9 us @ 87-88% DRAM SOL (~6.9-7.0 TB/s)
// Full sweep: batch depth (1/2/4/thread), 128b vs 256b loads, block 256/512,
// default vs streaming cache policy, flat vs persistent grid. This config
// wins or ties all; persistent grid-stride regressed to 120.5us (flat
// oversubscription keeps memory queues fuller).
// Traffic (512MB read + 256MB write fp32) is irreducible; the ~12% gap to
// 8TB/s spec is DRAM-controller-side (2R:1W bus turnaround + refresh).

#define TAU 0.25f

__device__ __forceinline__ float4 lif4(float4 xv, float4 lv, float thre)
{
    float4 ov;
    float u = xv.x + lv.x;                 // t=0: u0=0 -> no decay term
    float o = (u > thre) ? u : 0.0f;
    ov.x = o;
    float reset = (o > thre) ? 0.0f : 1.0f;
    u = TAU * u * reset + xv.y + lv.y;     // t=1
    o = (u > thre) ? u : 0.0f;
    ov.y = o;
    reset = (o > thre) ? 0.0f : 1.0f;
    u = TAU * u * reset + xv.z + lv.z;     // t=2
    o = (u > thre) ? u : 0.0f;
    ov.z = o;
    reset = (o > thre) ? 0.0f : 1.0f;
    u = TAU * u * reset + xv.w + lv.w;     // t=3
    o = (u > thre) ? u : 0.0f;
    ov.w = o;
    return ov;
}

// Fast path: grid*blockDim*2 == n exactly; no predicates.
__global__ __launch_bounds__(256) void lif_kernel_exact(
    const float4* __restrict__ x,
    const float4* __restrict__ lat,
    const float* __restrict__ w,
    float4* __restrict__ out)
{
    int i0 = blockIdx.x * (blockDim.x * 2) + threadIdx.x;
    int i1 = i0 + blockDim.x;   // second contiguous 512B warp segment

    const float thre = tanhf(w[0]);

    // Front-batch all 4 loads (read-once: evict-first)
    float4 x0 = __ldcs(&x[i0]);
    float4 l0 = __ldcs(&lat[i0]);
    float4 x1 = __ldcs(&x[i1]);
    float4 l1 = __ldcs(&lat[i1]);

    __stcs(&out[i0], lif4(x0, l0, thre));
    __stcs(&out[i1], lif4(x1, l1, thre));
}

// Fallback: one float4 per thread, predicated (general sizes).
__global__ __launch_bounds__(256) void lif_kernel_f4(
    const float4* __restrict__ x,
    const float4* __restrict__ lat,
    const float* __restrict__ w,
    float4* __restrict__ out,
    int n)
{
    int i = blockIdx.x * blockDim.x + threadIdx.x;
    if (i >= n) return;
    const float thre = tanhf(w[0]);
    float4 xv = __ldcs(&x[i]);
    float4 lv = __ldcs(&lat[i]);
    __stcs(&out[i], lif4(xv, lv, thre));
}

extern "C" void kernel_launch(void* const* d_in, const int* in_sizes, int n_in,
                              void* d_out, int out_size)
{
    const float4* x   = (const float4*)d_in[0];  // [B, N, T] float32, T=4
    const float4* lat = (const float4*)d_in[1];
    const float*  w   = (const float*)d_in[2];   // scalar
    float4* out = (float4*)d_out;

    int n = in_sizes[0] / 4;     // neurons (B*N); one float4 each
    int block = 256;
    int per_block = block * 2;   // 2 neurons per thread

    if (n % per_block == 0) {
        lif_kernel_exact<<<n / per_block, block>>>(x, lat, w, out);
    } else {
        lif_kernel_f4<<<(n + block - 1) / block, block>>>(x, lat, w, out, n);
    }
}